// round 1
// baseline (speedup 1.0000x reference)
#include <cuda_runtime.h>
#include <math.h>

// Problem constants: x[B,T,C] @ W[C,H] -> q,k,v; softmax(q k^T * C^-0.5) v
#define B_ 8
#define T_ 2048
#define C_ 512
#define H_ 64
#define SCALE 0.04419417382415922f   // 512^-0.5

// Scratch for Q, K, V: [B*T, H] each = 4 MB each (allocation-free rule: __device__ globals)
__device__ float g_Q[B_ * T_ * H_];
__device__ float g_K[B_ * T_ * H_];
__device__ float g_V[B_ * T_ * H_];

// ---------------------------------------------------------------------------
// Kernel 1: QKV projection. GEMM [16384 x 512] @ [512 x 64] for each of 3 W's.
// Block: 64 rows x 64 cols, K-tile 32. 256 threads, 4x4 microtile each.
// ---------------------------------------------------------------------------
#define XS_STRIDE 36   // 32 + 4 pad (bank-conflict-free for row-varying reads)
#define WS_STRIDE 68   // 64 + 4 pad

__global__ __launch_bounds__(256, 2)
void proj_kernel(const float* __restrict__ x,
                 const float* __restrict__ Wq,
                 const float* __restrict__ Wk,
                 const float* __restrict__ Wv) {
    __shared__ float Xs[64 * XS_STRIDE];
    __shared__ float Ws[32 * WS_STRIDE];

    const int which = blockIdx.y;
    const float* W = (which == 0) ? Wq : (which == 1) ? Wk : Wv;
    float* out = (which == 0) ? g_Q : (which == 1) ? g_K : g_V;

    const int tid = threadIdx.x;
    const int ty = tid >> 4;          // 0..15 -> rows ty*4..ty*4+3
    const int tx = tid & 15;          // 0..15 -> cols tx*4..tx*4+3
    const int row0 = blockIdx.x * 64; // row tile base in [0, 16384)

    float acc[4][4];
#pragma unroll
    for (int i = 0; i < 4; i++)
#pragma unroll
        for (int j = 0; j < 4; j++) acc[i][j] = 0.0f;

    for (int k0 = 0; k0 < C_; k0 += 32) {
        // Load X tile 64x32 (512 float4, 2 per thread)
#pragma unroll
        for (int i = 0; i < 2; i++) {
            int e = tid + i * 256;
            int r = e >> 3;          // 0..63
            int c4 = e & 7;          // 0..7
            float4 v = *(const float4*)(x + (size_t)(row0 + r) * C_ + k0 + c4 * 4);
            *(float4*)(Xs + r * XS_STRIDE + c4 * 4) = v;
        }
        // Load W tile 32x64 (512 float4, 2 per thread)
#pragma unroll
        for (int i = 0; i < 2; i++) {
            int e = tid + i * 256;
            int r = e >> 4;          // 0..31
            int c4 = e & 15;         // 0..15
            float4 v = *(const float4*)(W + (size_t)(k0 + r) * H_ + c4 * 4);
            *(float4*)(Ws + r * WS_STRIDE + c4 * 4) = v;
        }
        __syncthreads();

#pragma unroll
        for (int kk = 0; kk < 32; kk++) {
            float a[4];
#pragma unroll
            for (int i = 0; i < 4; i++) a[i] = Xs[(ty * 4 + i) * XS_STRIDE + kk];
            float4 b = *(const float4*)(Ws + kk * WS_STRIDE + tx * 4);
#pragma unroll
            for (int i = 0; i < 4; i++) {
                acc[i][0] = fmaf(a[i], b.x, acc[i][0]);
                acc[i][1] = fmaf(a[i], b.y, acc[i][1]);
                acc[i][2] = fmaf(a[i], b.z, acc[i][2]);
                acc[i][3] = fmaf(a[i], b.w, acc[i][3]);
            }
        }
        __syncthreads();
    }

#pragma unroll
    for (int i = 0; i < 4; i++) {
        float4 v = make_float4(acc[i][0], acc[i][1], acc[i][2], acc[i][3]);
        *(float4*)(out + (size_t)(row0 + ty * 4 + i) * H_ + tx * 4) = v;
    }
}

// ---------------------------------------------------------------------------
// Kernel 2: fused flash attention. One block = 64 query rows of one batch.
// Online softmax over 32 key tiles of 64. 256 threads, 4x4 microtiles.
// Smem: Q/K/V/P tiles, 64 x (64+4) floats each = 69632 B (dynamic).
// ---------------------------------------------------------------------------
#define TS 68   // tile stride (64 + 4 pad)

__global__ __launch_bounds__(256, 2)
void attn_kernel(float* __restrict__ out) {
    extern __shared__ float sm[];
    float* Qs = sm;                 // 64*TS
    float* Ks = Qs + 64 * TS;
    float* Vs = Ks + 64 * TS;
    float* Ps = Vs + 64 * TS;

    const int tid = threadIdx.x;
    const int ty = tid >> 4;        // query-row group: rows ty*4..+3
    const int tx = tid & 15;        // col group
    const int b = blockIdx.y;
    const int qt = blockIdx.x;

    // Load Q tile (pre-scaled by SCALE): 1024 float4, 4 per thread
    const float* Qg = g_Q + ((size_t)b * T_ + qt * 64) * H_;
#pragma unroll
    for (int i = 0; i < 4; i++) {
        int e = tid + i * 256;
        int r = e >> 4;             // 0..63
        int c4 = e & 15;            // 0..15
        float4 v = *(const float4*)(Qg + (size_t)r * H_ + c4 * 4);
        v.x *= SCALE; v.y *= SCALE; v.z *= SCALE; v.w *= SCALE;
        *(float4*)(Qs + r * TS + c4 * 4) = v;
    }

    float m[4], l[4], acc[4][4];
#pragma unroll
    for (int i = 0; i < 4; i++) {
        m[i] = -1e30f;
        l[i] = 0.0f;
#pragma unroll
        for (int j = 0; j < 4; j++) acc[i][j] = 0.0f;
    }

    const float* Kg = g_K + (size_t)b * T_ * H_;
    const float* Vg = g_V + (size_t)b * T_ * H_;

    for (int kt = 0; kt < T_ / 64; kt++) {
        // Load K and V tiles (64x64 each; 4 float4 per thread per tile)
        const float* Kt = Kg + (size_t)kt * 64 * H_;
        const float* Vt = Vg + (size_t)kt * 64 * H_;
#pragma unroll
        for (int i = 0; i < 4; i++) {
            int e = tid + i * 256;
            int r = e >> 4;
            int c4 = e & 15;
            *(float4*)(Ks + r * TS + c4 * 4) = *(const float4*)(Kt + (size_t)r * H_ + c4 * 4);
            *(float4*)(Vs + r * TS + c4 * 4) = *(const float4*)(Vt + (size_t)r * H_ + c4 * 4);
        }
        __syncthreads();

        // S = Qs (scaled) @ Ks^T : 4x4 per thread, float4 over head dim
        float s[4][4];
#pragma unroll
        for (int i = 0; i < 4; i++)
#pragma unroll
            for (int j = 0; j < 4; j++) s[i][j] = 0.0f;

#pragma unroll
        for (int h4 = 0; h4 < 16; h4++) {
            float4 qa[4], kb[4];
#pragma unroll
            for (int i = 0; i < 4; i++)
                qa[i] = *(const float4*)(Qs + (ty * 4 + i) * TS + h4 * 4);
#pragma unroll
            for (int j = 0; j < 4; j++)
                kb[j] = *(const float4*)(Ks + (tx * 4 + j) * TS + h4 * 4);
#pragma unroll
            for (int i = 0; i < 4; i++)
#pragma unroll
                for (int j = 0; j < 4; j++) {
                    s[i][j] = fmaf(qa[i].x, kb[j].x, s[i][j]);
                    s[i][j] = fmaf(qa[i].y, kb[j].y, s[i][j]);
                    s[i][j] = fmaf(qa[i].z, kb[j].z, s[i][j]);
                    s[i][j] = fmaf(qa[i].w, kb[j].w, s[i][j]);
                }
        }

        // Online softmax update. Row owned by 16 threads (same ty-group lanes).
#pragma unroll
        for (int i = 0; i < 4; i++) {
            float rmax = fmaxf(fmaxf(s[i][0], s[i][1]), fmaxf(s[i][2], s[i][3]));
#pragma unroll
            for (int off = 8; off >= 1; off >>= 1)
                rmax = fmaxf(rmax, __shfl_xor_sync(0xffffffffu, rmax, off));
            float mn = fmaxf(m[i], rmax);
            float alpha = __expf(m[i] - mn);
            m[i] = mn;
            float ps = 0.0f;
#pragma unroll
            for (int j = 0; j < 4; j++) {
                s[i][j] = __expf(s[i][j] - mn);
                ps += s[i][j];
            }
#pragma unroll
            for (int off = 8; off >= 1; off >>= 1)
                ps += __shfl_xor_sync(0xffffffffu, ps, off);
            l[i] = l[i] * alpha + ps;
#pragma unroll
            for (int j = 0; j < 4; j++) acc[i][j] *= alpha;
            // Stash P fragment to smem for the PV GEMM
            float4 pv = make_float4(s[i][0], s[i][1], s[i][2], s[i][3]);
            *(float4*)(Ps + (ty * 4 + i) * TS + tx * 4) = pv;
        }
        __syncthreads();

        // O += P @ V : acc rows ty*4..+3, cols tx*4..+3
#pragma unroll
        for (int c4 = 0; c4 < 16; c4++) {
            float4 p[4], vv[4];
#pragma unroll
            for (int i = 0; i < 4; i++)
                p[i] = *(const float4*)(Ps + (ty * 4 + i) * TS + c4 * 4);
#pragma unroll
            for (int cc = 0; cc < 4; cc++)
                vv[cc] = *(const float4*)(Vs + (c4 * 4 + cc) * TS + tx * 4);
#pragma unroll
            for (int i = 0; i < 4; i++) {
                acc[i][0] = fmaf(p[i].x, vv[0].x, acc[i][0]);
                acc[i][1] = fmaf(p[i].x, vv[0].y, acc[i][1]);
                acc[i][2] = fmaf(p[i].x, vv[0].z, acc[i][2]);
                acc[i][3] = fmaf(p[i].x, vv[0].w, acc[i][3]);
                acc[i][0] = fmaf(p[i].y, vv[1].x, acc[i][0]);
                acc[i][1] = fmaf(p[i].y, vv[1].y, acc[i][1]);
                acc[i][2] = fmaf(p[i].y, vv[1].z, acc[i][2]);
                acc[i][3] = fmaf(p[i].y, vv[1].w, acc[i][3]);
                acc[i][0] = fmaf(p[i].z, vv[2].x, acc[i][0]);
                acc[i][1] = fmaf(p[i].z, vv[2].y, acc[i][1]);
                acc[i][2] = fmaf(p[i].z, vv[2].z, acc[i][2]);
                acc[i][3] = fmaf(p[i].z, vv[2].w, acc[i][3]);
                acc[i][0] = fmaf(p[i].w, vv[3].x, acc[i][0]);
                acc[i][1] = fmaf(p[i].w, vv[3].y, acc[i][1]);
                acc[i][2] = fmaf(p[i].w, vv[3].z, acc[i][2]);
                acc[i][3] = fmaf(p[i].w, vv[3].w, acc[i][3]);
            }
        }
        __syncthreads();   // done reading Ks/Vs/Ps; safe to overwrite next iter
    }

    // Epilogue: normalize by l and write [B, T, H]
#pragma unroll
    for (int i = 0; i < 4; i++) {
        float rl = 1.0f / l[i];
        float4 v = make_float4(acc[i][0] * rl, acc[i][1] * rl,
                               acc[i][2] * rl, acc[i][3] * rl);
        size_t row = (size_t)b * T_ + qt * 64 + ty * 4 + i;
        *(float4*)(out + row * H_ + tx * 4) = v;
    }
}

// ---------------------------------------------------------------------------
extern "C" void kernel_launch(void* const* d_in, const int* in_sizes, int n_in,
                              void* d_out, int out_size) {
    const float* x  = (const float*)d_in[0];
    const float* Wq = (const float*)d_in[1];
    const float* Wk = (const float*)d_in[2];
    const float* Wv = (const float*)d_in[3];
    float* out = (float*)d_out;

    const int ATTN_SMEM = 4 * 64 * TS * sizeof(float);  // 69632 B
    static bool attr_set = false;
    // cudaFuncSetAttribute is idempotent & not a stream op; safe under capture.
    cudaFuncSetAttribute(attn_kernel, cudaFuncAttributeMaxDynamicSharedMemorySize,
                         ATTN_SMEM);
    (void)attr_set;

    dim3 pg(B_ * T_ / 64, 3);        // 256 row-tiles x {Wq,Wk,Wv}
    proj_kernel<<<pg, 256>>>(x, Wq, Wk, Wv);

    dim3 ag(T_ / 64, B_);            // 32 q-tiles x 8 batches
    attn_kernel<<<ag, 256, ATTN_SMEM>>>(out);
}

// round 3
// speedup vs baseline: 1.3395x; 1.3395x over previous
#include <cuda_runtime.h>
#include <math.h>

// Problem constants: x[B,T,C] @ W[C,H] -> q,k,v; softmax(q k^T * C^-0.5) v
#define B_ 8
#define T_ 2048
#define C_ 512
#define H_ 64
#define SCALE 0.04419417382415922f   // 512^-0.5

// Scratch for Q, K, V: [B*T, H] each = 4 MB each (allocation-free rule: __device__ globals)
__device__ float g_Q[B_ * T_ * H_];
__device__ float g_K[B_ * T_ * H_];
__device__ float g_V[B_ * T_ * H_];

// ---------------------------------------------------------------------------
// Kernel 1: QKV projection. GEMM [16384 x 512] @ [512 x 64] for each of 3 W's.
// Block: 64 rows x 64 cols, K-tile 32. 256 threads, 4x4 microtile each.
// (Already at its FMA roofline ~85us; unchanged this round.)
// ---------------------------------------------------------------------------
#define XS_STRIDE 36   // 32 + 4 pad
#define WS_STRIDE 68   // 64 + 4 pad (68*4B = 17*16B, float4-aligned)

__global__ __launch_bounds__(256, 2)
void proj_kernel(const float* __restrict__ x,
                 const float* __restrict__ Wq,
                 const float* __restrict__ Wk,
                 const float* __restrict__ Wv) {
    __shared__ float Xs[64 * XS_STRIDE];
    __shared__ float Ws[32 * WS_STRIDE];

    const int which = blockIdx.y;
    const float* W = (which == 0) ? Wq : (which == 1) ? Wk : Wv;
    float* out = (which == 0) ? g_Q : (which == 1) ? g_K : g_V;

    const int tid = threadIdx.x;
    const int ty = tid >> 4;
    const int tx = tid & 15;
    const int row0 = blockIdx.x * 64;

    float acc[4][4];
#pragma unroll
    for (int i = 0; i < 4; i++)
#pragma unroll
        for (int j = 0; j < 4; j++) acc[i][j] = 0.0f;

    for (int k0 = 0; k0 < C_; k0 += 32) {
#pragma unroll
        for (int i = 0; i < 2; i++) {
            int e = tid + i * 256;
            int r = e >> 3;
            int c4 = e & 7;
            float4 v = *(const float4*)(x + (size_t)(row0 + r) * C_ + k0 + c4 * 4);
            *(float4*)(Xs + r * XS_STRIDE + c4 * 4) = v;
        }
#pragma unroll
        for (int i = 0; i < 2; i++) {
            int e = tid + i * 256;
            int r = e >> 4;
            int c4 = e & 15;
            float4 v = *(const float4*)(W + (size_t)(k0 + r) * H_ + c4 * 4);
            *(float4*)(Ws + r * WS_STRIDE + c4 * 4) = v;
        }
        __syncthreads();

#pragma unroll
        for (int kk = 0; kk < 32; kk++) {
            float a[4];
#pragma unroll
            for (int i = 0; i < 4; i++) a[i] = Xs[(ty * 4 + i) * XS_STRIDE + kk];
            float4 b = *(const float4*)(Ws + kk * WS_STRIDE + tx * 4);
#pragma unroll
            for (int i = 0; i < 4; i++) {
                acc[i][0] = fmaf(a[i], b.x, acc[i][0]);
                acc[i][1] = fmaf(a[i], b.y, acc[i][1]);
                acc[i][2] = fmaf(a[i], b.z, acc[i][2]);
                acc[i][3] = fmaf(a[i], b.w, acc[i][3]);
            }
        }
        __syncthreads();
    }

#pragma unroll
    for (int i = 0; i < 4; i++) {
        float4 v = make_float4(acc[i][0], acc[i][1], acc[i][2], acc[i][3]);
        *(float4*)(out + (size_t)(row0 + ty * 4 + i) * H_ + tx * 4) = v;
    }
}

// ---------------------------------------------------------------------------
// Kernel 2: fused flash attention, XOR-swizzled smem tiles (conflict-free).
// Tile layout: 64 rows x 64 floats (no pad). 16B chunk c of row r lives at
// chunk position c ^ ((r>>2)&7). This makes the K-fragment loads in QK^T
// (row = tx*4+j, chunk = h4) hit chunk h4 ^ (tx&7): 8 distinct bank groups
// per 8-lane LDS.128 phase -> conflict-free. All other accesses (stores,
// V loads, P loads/stores, Q broadcasts) are also conflict-free under it.
// ---------------------------------------------------------------------------
__device__ __forceinline__ int sw_off(int r, int c4) {
    // r: row 0..63, c4: 16B-chunk index 0..15 -> float offset
    return (r << 6) + (((c4 ^ ((r >> 2) & 7))) << 2);
}

__global__ __launch_bounds__(256, 2)
void attn_kernel(float* __restrict__ out) {
    extern __shared__ float sm[];
    float* Qs = sm;                 // 64*64
    float* Ks = Qs + 64 * 64;
    float* Vs = Ks + 64 * 64;
    float* Ps = Vs + 64 * 64;

    const int tid = threadIdx.x;
    const int ty = tid >> 4;        // query-row group: rows ty*4..+3
    const int tx = tid & 15;        // col group
    const int b = blockIdx.y;
    const int qt = blockIdx.x;

    // Load Q tile (pre-scaled by SCALE), swizzled store
    const float* Qg = g_Q + ((size_t)b * T_ + qt * 64) * H_;
#pragma unroll
    for (int i = 0; i < 4; i++) {
        int e = tid + i * 256;
        int r = e >> 4;             // 0..63
        int c4 = e & 15;            // 0..15
        float4 v = *(const float4*)(Qg + (size_t)r * H_ + c4 * 4);
        v.x *= SCALE; v.y *= SCALE; v.z *= SCALE; v.w *= SCALE;
        *(float4*)(Qs + sw_off(r, c4)) = v;
    }

    float m[4], l[4], acc[4][4];
#pragma unroll
    for (int i = 0; i < 4; i++) {
        m[i] = -1e30f;
        l[i] = 0.0f;
#pragma unroll
        for (int j = 0; j < 4; j++) acc[i][j] = 0.0f;
    }

    const float* Kg = g_K + (size_t)b * T_ * H_;
    const float* Vg = g_V + (size_t)b * T_ * H_;

    for (int kt = 0; kt < T_ / 64; kt++) {
        const float* Kt = Kg + (size_t)kt * 64 * H_;
        const float* Vt = Vg + (size_t)kt * 64 * H_;
#pragma unroll
        for (int i = 0; i < 4; i++) {
            int e = tid + i * 256;
            int r = e >> 4;
            int c4 = e & 15;
            int so = sw_off(r, c4);
            *(float4*)(Ks + so) = *(const float4*)(Kt + (size_t)r * H_ + c4 * 4);
            *(float4*)(Vs + so) = *(const float4*)(Vt + (size_t)r * H_ + c4 * 4);
        }
        __syncthreads();

        // S = Qs (scaled) @ Ks^T : 4x4 per thread, float4 over head dim
        float s[4][4];
#pragma unroll
        for (int i = 0; i < 4; i++)
#pragma unroll
            for (int j = 0; j < 4; j++) s[i][j] = 0.0f;

#pragma unroll
        for (int h4 = 0; h4 < 16; h4++) {
            float4 qa[4], kb[4];
#pragma unroll
            for (int i = 0; i < 4; i++)
                qa[i] = *(const float4*)(Qs + sw_off(ty * 4 + i, h4));
#pragma unroll
            for (int j = 0; j < 4; j++)
                kb[j] = *(const float4*)(Ks + sw_off(tx * 4 + j, h4));
#pragma unroll
            for (int i = 0; i < 4; i++)
#pragma unroll
                for (int j = 0; j < 4; j++) {
                    s[i][j] = fmaf(qa[i].x, kb[j].x, s[i][j]);
                    s[i][j] = fmaf(qa[i].y, kb[j].y, s[i][j]);
                    s[i][j] = fmaf(qa[i].z, kb[j].z, s[i][j]);
                    s[i][j] = fmaf(qa[i].w, kb[j].w, s[i][j]);
                }
        }

        // Online softmax update. Row owned by 16 threads (same ty-group lanes).
#pragma unroll
        for (int i = 0; i < 4; i++) {
            float rmax = fmaxf(fmaxf(s[i][0], s[i][1]), fmaxf(s[i][2], s[i][3]));
#pragma unroll
            for (int off = 8; off >= 1; off >>= 1)
                rmax = fmaxf(rmax, __shfl_xor_sync(0xffffffffu, rmax, off));
            float mn = fmaxf(m[i], rmax);
            float alpha = __expf(m[i] - mn);
            m[i] = mn;
            float ps = 0.0f;
#pragma unroll
            for (int j = 0; j < 4; j++) {
                s[i][j] = __expf(s[i][j] - mn);
                ps += s[i][j];
            }
#pragma unroll
            for (int off = 8; off >= 1; off >>= 1)
                ps += __shfl_xor_sync(0xffffffffu, ps, off);
            l[i] = l[i] * alpha + ps;
#pragma unroll
            for (int j = 0; j < 4; j++) acc[i][j] *= alpha;
            float4 pv = make_float4(s[i][0], s[i][1], s[i][2], s[i][3]);
            *(float4*)(Ps + sw_off(ty * 4 + i, tx)) = pv;
        }
        // P rows ty*4+i are read back only by lanes of the SAME ty-group
        // (same warp) -> warp-scope sync suffices here.
        __syncwarp();

        // O += P @ V : acc rows ty*4..+3, cols tx*4..+3
#pragma unroll
        for (int c4 = 0; c4 < 16; c4++) {
            float4 p[4], vv[4];
#pragma unroll
            for (int i = 0; i < 4; i++)
                p[i] = *(const float4*)(Ps + sw_off(ty * 4 + i, c4));
#pragma unroll
            for (int cc = 0; cc < 4; cc++)
                vv[cc] = *(const float4*)(Vs + sw_off(c4 * 4 + cc, tx));
#pragma unroll
            for (int i = 0; i < 4; i++) {
                acc[i][0] = fmaf(p[i].x, vv[0].x, acc[i][0]);
                acc[i][1] = fmaf(p[i].x, vv[0].y, acc[i][1]);
                acc[i][2] = fmaf(p[i].x, vv[0].z, acc[i][2]);
                acc[i][3] = fmaf(p[i].x, vv[0].w, acc[i][3]);
                acc[i][0] = fmaf(p[i].y, vv[1].x, acc[i][0]);
                acc[i][1] = fmaf(p[i].y, vv[1].y, acc[i][1]);
                acc[i][2] = fmaf(p[i].y, vv[1].z, acc[i][2]);
                acc[i][3] = fmaf(p[i].y, vv[1].w, acc[i][3]);
                acc[i][0] = fmaf(p[i].z, vv[2].x, acc[i][0]);
                acc[i][1] = fmaf(p[i].z, vv[2].y, acc[i][1]);
                acc[i][2] = fmaf(p[i].z, vv[2].z, acc[i][2]);
                acc[i][3] = fmaf(p[i].z, vv[2].w, acc[i][3]);
                acc[i][0] = fmaf(p[i].w, vv[3].x, acc[i][0]);
                acc[i][1] = fmaf(p[i].w, vv[3].y, acc[i][1]);
                acc[i][2] = fmaf(p[i].w, vv[3].z, acc[i][2]);
                acc[i][3] = fmaf(p[i].w, vv[3].w, acc[i][3]);
            }
        }
        __syncthreads();   // done reading Ks/Vs/Ps; safe to overwrite next iter
    }

    // Epilogue: normalize by l and write [B, T, H]
#pragma unroll
    for (int i = 0; i < 4; i++) {
        float rl = 1.0f / l[i];
        float4 v = make_float4(acc[i][0] * rl, acc[i][1] * rl,
                               acc[i][2] * rl, acc[i][3] * rl);
        size_t row = (size_t)b * T_ + qt * 64 + ty * 4 + i;
        *(float4*)(out + row * H_ + tx * 4) = v;
    }
}

// ---------------------------------------------------------------------------
extern "C" void kernel_launch(void* const* d_in, const int* in_sizes, int n_in,
                              void* d_out, int out_size) {
    const float* x  = (const float*)d_in[0];
    const float* Wq = (const float*)d_in[1];
    const float* Wk = (const float*)d_in[2];
    const float* Wv = (const float*)d_in[3];
    float* out = (float*)d_out;

    const int ATTN_SMEM = 4 * 64 * 64 * sizeof(float);  // 65536 B
    cudaFuncSetAttribute(attn_kernel, cudaFuncAttributeMaxDynamicSharedMemorySize,
                         ATTN_SMEM);

    dim3 pg(B_ * T_ / 64, 3);        // 256 row-tiles x {Wq,Wk,Wv}
    proj_kernel<<<pg, 256>>>(x, Wq, Wk, Wv);

    dim3 ag(T_ / 64, B_);            // 32 q-tiles x 8 batches
    attn_kernel<<<ag, 256, ATTN_SMEM>>>(out);
}